// round 4
// baseline (speedup 1.0000x reference)
#include <cuda_runtime.h>
#include <cuda_bf16.h>
#include <math.h>

#define NN  50000
#define EE  800000
#define INC 512
#define HH  64
#define OC  40
#define NL  64
#define NBLK ((NN + 1023) / 1024)   // 49 scan blocks

// ---------------- device scratch (static, no allocation) ----------------
__device__ float g_dinv[NN];
__device__ int   g_cnt[NN];
__device__ int   g_rowptr[NN + 1];
__device__ int   g_bsum[NBLK];
__device__ int   g_boff[NBLK];
__device__ int   g_fill[NN];
__device__ int2  g_edge[EE];        // (col, val bits) packed
__device__ float g_x0[NN * HH];
__device__ float g_hbuf[2][NN * HH];
__device__ int   g_is64;

// ---------------- lin1: h = relu(x @ W1 + b1) ----------------
// 256 threads = 128 nodes x 2 column-halves; acc[32]/thread.
__global__ __launch_bounds__(256) void k_lin1(const float* __restrict__ x,
                                              const float* __restrict__ w1,
                                              const float* __restrict__ b1) {
    __shared__ float xsT[32][129];
    __shared__ float ws[32 * 64];
    int t = threadIdx.x;
    int half = t >> 7;        // 0: cols 0-31, 1: cols 32-63
    int nl = t & 127;         // local node
    int node0 = blockIdx.x * 128;

    float acc[32];
#pragma unroll
    for (int c = 0; c < 32; c++) acc[c] = 0.f;

    for (int kt = 0; kt < INC; kt += 32) {
        for (int i = t; i < 32 * 64; i += 256)
            ws[i] = w1[(kt + (i >> 6)) * 64 + (i & 63)];
        // x tile transposed: 128 nodes x 32 k  (1024 float4, 4/thread)
        for (int i = t; i < 1024; i += 256) {
            int r = i >> 3, c4 = i & 7;
            int node = node0 + r;
            float4 v = make_float4(0.f, 0.f, 0.f, 0.f);
            if (node < NN)
                v = *(const float4*)&x[(size_t)node * INC + kt + c4 * 4];
            xsT[c4 * 4 + 0][r] = v.x;
            xsT[c4 * 4 + 1][r] = v.y;
            xsT[c4 * 4 + 2][r] = v.z;
            xsT[c4 * 4 + 3][r] = v.w;
        }
        __syncthreads();
#pragma unroll 4
        for (int k = 0; k < 32; k++) {
            float xv = xsT[k][nl];
            const float4* wr = (const float4*)&ws[k * 64 + half * 32];
#pragma unroll
            for (int c4 = 0; c4 < 8; c4++) {
                float4 w4 = wr[c4];
                acc[c4 * 4 + 0] += xv * w4.x;
                acc[c4 * 4 + 1] += xv * w4.y;
                acc[c4 * 4 + 2] += xv * w4.z;
                acc[c4 * 4 + 3] += xv * w4.w;
            }
        }
        __syncthreads();
    }
    int node = node0 + nl;
    if (node < NN) {
        float* px = &g_x0[node * 64 + half * 32];
        float* ph = &g_hbuf[0][node * 64 + half * 32];
#pragma unroll
        for (int c4 = 0; c4 < 8; c4++) {
            float4 v;
            v.x = fmaxf(acc[c4 * 4 + 0] + b1[half * 32 + c4 * 4 + 0], 0.f);
            v.y = fmaxf(acc[c4 * 4 + 1] + b1[half * 32 + c4 * 4 + 1], 0.f);
            v.z = fmaxf(acc[c4 * 4 + 2] + b1[half * 32 + c4 * 4 + 2], 0.f);
            v.w = fmaxf(acc[c4 * 4 + 3] + b1[half * 32 + c4 * 4 + 3], 0.f);
            *(float4*)&px[c4 * 4] = v;
            *(float4*)&ph[c4 * 4] = v;
        }
    }
}

// ---------------- preprocessing ----------------
__global__ void k_zero_detect(const int* ei32) {
    int i = blockIdx.x * blockDim.x + threadIdx.x;
    if (i < NN) g_cnt[i] = 0;
    if (i == 0) {
        int all0 = 1;
        for (int j = 0; j < 64; j++)
            if (ei32[2 * j + 1] != 0) all0 = 0;
        g_is64 = all0;
    }
}

__global__ void k_count(const void* eiv) {
    int e = blockIdx.x * blockDim.x + threadIdx.x;
    if (e >= EE) return;
    int d;
    if (g_is64) d = (int)((const long long*)eiv)[EE + e];
    else        d = ((const int*)eiv)[EE + e];
    atomicAdd(&g_cnt[d], 1);
}

// 3-phase scan (round-2 version, 4.9us)
__global__ __launch_bounds__(1024) void k_scanA() {
    __shared__ int wsum[32];
    int t = threadIdx.x, b = blockIdx.x;
    int i = b * 1024 + t;
    int v = (i < NN) ? g_cnt[i] : 0;
    int lane = t & 31, wid = t >> 5;
    int s = v;
#pragma unroll
    for (int o = 1; o < 32; o <<= 1) {
        int u = __shfl_up_sync(0xffffffffu, s, o);
        if (lane >= o) s += u;
    }
    if (lane == 31) wsum[wid] = s;
    __syncthreads();
    if (wid == 0) {
        int ws = wsum[lane];
#pragma unroll
        for (int o = 1; o < 32; o <<= 1) {
            int u = __shfl_up_sync(0xffffffffu, ws, o);
            if (lane >= o) ws += u;
        }
        wsum[lane] = ws;
    }
    __syncthreads();
    int excl = s - v + (wid > 0 ? wsum[wid - 1] : 0);
    if (i < NN) g_rowptr[i] = excl;
    if (t == 1023) g_bsum[b] = excl + v;
}

__global__ void k_scanB() {
    int t = threadIdx.x;  // 64 threads
    __shared__ int sh[64];
    sh[t] = (t < NBLK) ? g_bsum[t] : 0;
    __syncthreads();
    for (int o = 1; o < 64; o <<= 1) {
        int u = (t >= o) ? sh[t - o] : 0;
        __syncthreads();
        sh[t] += u;
        __syncthreads();
    }
    if (t < NBLK) g_boff[t] = sh[t] - g_bsum[t];
}

__global__ void k_scanC() {
    int i = blockIdx.x * blockDim.x + threadIdx.x;
    if (i < NN) {
        g_rowptr[i] += g_boff[i >> 10];
        g_dinv[i] = rsqrtf((float)(g_cnt[i] + 1));
        g_fill[i] = 0;
    }
    if (i == 0) g_rowptr[NN] = EE;
}

__global__ void k_fill(const void* eiv) {
    int e = blockIdx.x * blockDim.x + threadIdx.x;
    if (e >= EE) return;
    int s, d;
    if (g_is64) {
        const long long* ei = (const long long*)eiv;
        s = (int)ei[e];
        d = (int)ei[EE + e];
    } else {
        const int* ei = (const int*)eiv;
        s = ei[e];
        d = ei[EE + e];
    }
    int pos = g_rowptr[d] + atomicAdd(&g_fill[d], 1);
    g_edge[pos] = make_int2(s, __float_as_int(g_dinv[s] * g_dinv[d]));
}

// ---------------- fused GCNII layer ----------------
// warp = 4 nodes; smem edge staging (no shfl), 8-wide gather, shared-W GEMM.
__global__ __launch_bounds__(256) void k_layer(const float* __restrict__ W,
                                               float beta, int p) {
    __shared__ float ws[64 * 64];
    __shared__ float4 zq[8][64];
    __shared__ int2 esm[8][32];
    int t = threadIdx.x, w = t >> 5, lane = t & 31;
    int l2 = lane * 2;
    for (int i = t; i < 4096; i += 256) ws[i] = W[i];
    __syncthreads();

    const float* __restrict__ hin = g_hbuf[p];
    float* __restrict__ hout = g_hbuf[p ^ 1];
    int base = (blockIdx.x * 8 + w) * 4;
    float ob = 1.f - beta;

    float z[4][2];
#pragma unroll
    for (int q = 0; q < 4; q++) {
        int node = base + q;
        if (node >= NN) { z[q][0] = 0.f; z[q][1] = 0.f; continue; }
        float di = g_dinv[node];
        float2 hme = *(const float2*)&hin[node * 64 + l2];
        float a0 = di * di * hme.x;
        float a1 = di * di * hme.y;
        float b0 = 0.f, b1 = 0.f, c0 = 0.f, c1 = 0.f, d0 = 0.f, d1 = 0.f;
        int e0 = g_rowptr[node], e1 = g_rowptr[node + 1];
        for (int eb = e0; eb < e1; eb += 32) {
            int ee = eb + lane;
            if (ee < e1) esm[w][lane] = g_edge[ee];
            __syncwarp();
            int cn = min(32, e1 - eb);
            int j = 0;
            for (; j + 7 < cn; j += 8) {
                int2 E0 = esm[w][j + 0];
                int2 E1 = esm[w][j + 1];
                int2 E2 = esm[w][j + 2];
                int2 E3 = esm[w][j + 3];
                int2 E4 = esm[w][j + 4];
                int2 E5 = esm[w][j + 5];
                int2 E6 = esm[w][j + 6];
                int2 E7 = esm[w][j + 7];
                float2 h0 = *(const float2*)&hin[E0.x * 64 + l2];
                float2 h1 = *(const float2*)&hin[E1.x * 64 + l2];
                float2 h2 = *(const float2*)&hin[E2.x * 64 + l2];
                float2 h3 = *(const float2*)&hin[E3.x * 64 + l2];
                float2 h4 = *(const float2*)&hin[E4.x * 64 + l2];
                float2 h5 = *(const float2*)&hin[E5.x * 64 + l2];
                float2 h6 = *(const float2*)&hin[E6.x * 64 + l2];
                float2 h7 = *(const float2*)&hin[E7.x * 64 + l2];
                float v0 = __int_as_float(E0.y), v1 = __int_as_float(E1.y);
                float v2 = __int_as_float(E2.y), v3 = __int_as_float(E3.y);
                float v4 = __int_as_float(E4.y), v5 = __int_as_float(E5.y);
                float v6 = __int_as_float(E6.y), v7 = __int_as_float(E7.y);
                a0 += v0 * h0.x; a1 += v0 * h0.y;
                b0 += v1 * h1.x; b1 += v1 * h1.y;
                c0 += v2 * h2.x; c1 += v2 * h2.y;
                d0 += v3 * h3.x; d1 += v3 * h3.y;
                a0 += v4 * h4.x; a1 += v4 * h4.y;
                b0 += v5 * h5.x; b1 += v5 * h5.y;
                c0 += v6 * h6.x; c1 += v6 * h6.y;
                d0 += v7 * h7.x; d1 += v7 * h7.y;
            }
            for (; j < cn; j++) {
                int2 E0 = esm[w][j];
                float2 h0 = *(const float2*)&hin[E0.x * 64 + l2];
                float v0 = __int_as_float(E0.y);
                a0 += v0 * h0.x; a1 += v0 * h0.y;
            }
            __syncwarp();
        }
        a0 += b0 + c0 + d0;
        a1 += b1 + c1 + d1;
        float2 x02 = *(const float2*)&g_x0[node * 64 + l2];
        z[q][0] = 0.5f * a0 + 0.5f * x02.x;
        z[q][1] = 0.5f * a1 + 0.5f * x02.y;
    }
    // stage z transposed: zq[k] = {zA[k], zB[k], zC[k], zD[k]}
    zq[w][l2]     = make_float4(z[0][0], z[1][0], z[2][0], z[3][0]);
    zq[w][l2 + 1] = make_float4(z[0][1], z[1][1], z[2][1], z[3][1]);
    __syncwarp();

    float4 s0 = make_float4(0.f, 0.f, 0.f, 0.f);
    float4 s1 = make_float4(0.f, 0.f, 0.f, 0.f);
#pragma unroll
    for (int k = 0; k < 64; k++) {
        float4 zk = zq[w][k];
        float2 wk = *(const float2*)&ws[k * 64 + l2];
        s0.x += zk.x * wk.x; s0.y += zk.y * wk.x;
        s0.z += zk.z * wk.x; s0.w += zk.w * wk.x;
        s1.x += zk.x * wk.y; s1.y += zk.y * wk.y;
        s1.z += zk.z * wk.y; s1.w += zk.w * wk.y;
    }
    float sc0[4] = {s0.x, s0.y, s0.z, s0.w};
    float sc1[4] = {s1.x, s1.y, s1.z, s1.w};
#pragma unroll
    for (int q = 0; q < 4; q++) {
        int node = base + q;
        if (node < NN) {
            float o0 = fmaxf(ob * z[q][0] + beta * sc0[q], 0.f);
            float o1 = fmaxf(ob * z[q][1] + beta * sc1[q], 0.f);
            *(float2*)&hout[node * 64 + l2] = make_float2(o0, o1);
        }
    }
}

// ---------------- output: lin2 + log_softmax ----------------
__global__ __launch_bounds__(256) void k_out(const float* __restrict__ w2,
                                             const float* __restrict__ b2,
                                             float* __restrict__ out) {
    __shared__ float ws[64 * OC];
    __shared__ float bs[OC];
    __shared__ float zsm[8][64];
    int t = threadIdx.x, w = t >> 5, lane = t & 31;
    for (int i = t; i < 64 * OC; i += 256) ws[i] = w2[i];
    if (t < OC) bs[t] = b2[t];
    __syncthreads();

    const float* h = g_hbuf[0];  // NL even -> final state in buffer 0
    int warpG = blockIdx.x * 8 + w;
    int nW = gridDim.x * 8;

    for (int node = warpG; node < NN; node += nW) {
        float2 h2 = *(const float2*)&h[node * 64 + lane * 2];
        *(float2*)&zsm[w][lane * 2] = h2;
        __syncwarp();
        int c0 = lane;
        int c1 = lane + 32;
        float v0 = bs[c0];
        float v1 = (lane < 8) ? bs[c1] : 0.f;
#pragma unroll
        for (int k = 0; k < 64; k++) {
            float zk = zsm[w][k];
            v0 += zk * ws[k * OC + c0];
            if (lane < 8) v1 += zk * ws[k * OC + c1];
        }
        float m = v0;
        if (lane < 8) m = fmaxf(m, v1);
#pragma unroll
        for (int o = 16; o > 0; o >>= 1)
            m = fmaxf(m, __shfl_xor_sync(0xffffffffu, m, o));
        float se = expf(v0 - m) + ((lane < 8) ? expf(v1 - m) : 0.f);
#pragma unroll
        for (int o = 16; o > 0; o >>= 1)
            se += __shfl_xor_sync(0xffffffffu, se, o);
        float lse = m + logf(se);
        out[node * OC + c0] = v0 - lse;
        if (lane < 8) out[node * OC + c1] = v1 - lse;
        __syncwarp();
    }
}

// ---------------- launch ----------------
extern "C" void kernel_launch(void* const* d_in, const int* in_sizes, int n_in,
                              void* d_out, int out_size) {
    (void)in_sizes; (void)n_in; (void)out_size;
    const float* x  = (const float*)d_in[0];
    const void*  ei = d_in[1];
    const float* w1 = (const float*)d_in[2];
    const float* b1 = (const float*)d_in[3];
    const float* cw = (const float*)d_in[4];
    const float* w2 = (const float*)d_in[5];
    const float* b2 = (const float*)d_in[6];
    float* out = (float*)d_out;

    k_lin1<<<(NN + 127) / 128, 256>>>(x, w1, b1);
    k_zero_detect<<<(NN + 1023) / 1024, 1024>>>((const int*)ei);
    k_count<<<(EE + 255) / 256, 256>>>(ei);
    k_scanA<<<NBLK, 1024>>>();
    k_scanB<<<1, 64>>>();
    k_scanC<<<(NN + 1023) / 1024, 1024>>>();
    k_fill<<<(EE + 255) / 256, 256>>>(ei);

    int lgrid = (NN + 31) / 32;   // 1 bundle of 4 nodes per warp
    for (int l = 0; l < NL; l++) {
        float beta = logf(1.0f / (float)(l + 1) + 1.0f);
        k_layer<<<lgrid, 256>>>(cw + (size_t)l * HH * HH, beta, l & 1);
    }
    k_out<<<512, 256>>>(w2, b2, out);
}

// round 5
// speedup vs baseline: 1.1569x; 1.1569x over previous
#include <cuda_runtime.h>
#include <cuda_bf16.h>
#include <math.h>

#define NN  50000
#define EE  800000
#define INC 512
#define HH  64
#define OC  40
#define NL  64
#define NBLK ((NN + 1023) / 1024)

// ---------------- device scratch ----------------
__device__ float g_dinv[NN];
__device__ int   g_cnt[NN];
__device__ int   g_rowptr[NN + 1];
__device__ int   g_bsum[NBLK];
__device__ int   g_boff[NBLK];
__device__ int   g_fill[NN];
__device__ int   g_col[EE];
__device__ float g_val[EE];
__device__ float g_x0[NN * HH];
__device__ float g_hbuf[2][NN * HH];
__device__ int   g_is64;

// ---------------- lin1 ----------------
__global__ __launch_bounds__(256) void k_lin1(const float* __restrict__ x,
                                              const float* __restrict__ w1,
                                              const float* __restrict__ b1) {
    __shared__ float xsT[32][129];
    __shared__ float ws[32 * 64];
    int t = threadIdx.x;
    int half = t >> 7;
    int nl = t & 127;
    int node0 = blockIdx.x * 128;

    float acc[32];
#pragma unroll
    for (int c = 0; c < 32; c++) acc[c] = 0.f;

    for (int kt = 0; kt < INC; kt += 32) {
        for (int i = t; i < 32 * 64; i += 256)
            ws[i] = w1[(kt + (i >> 6)) * 64 + (i & 63)];
        for (int i = t; i < 1024; i += 256) {
            int r = i >> 3, c4 = i & 7;
            int node = node0 + r;
            float4 v = make_float4(0.f, 0.f, 0.f, 0.f);
            if (node < NN)
                v = *(const float4*)&x[(size_t)node * INC + kt + c4 * 4];
            xsT[c4 * 4 + 0][r] = v.x;
            xsT[c4 * 4 + 1][r] = v.y;
            xsT[c4 * 4 + 2][r] = v.z;
            xsT[c4 * 4 + 3][r] = v.w;
        }
        __syncthreads();
#pragma unroll 4
        for (int k = 0; k < 32; k++) {
            float xv = xsT[k][nl];
            const float4* wr = (const float4*)&ws[k * 64 + half * 32];
#pragma unroll
            for (int c4 = 0; c4 < 8; c4++) {
                float4 w4 = wr[c4];
                acc[c4 * 4 + 0] += xv * w4.x;
                acc[c4 * 4 + 1] += xv * w4.y;
                acc[c4 * 4 + 2] += xv * w4.z;
                acc[c4 * 4 + 3] += xv * w4.w;
            }
        }
        __syncthreads();
    }
    int node = node0 + nl;
    if (node < NN) {
        float* px = &g_x0[node * 64 + half * 32];
        float* ph = &g_hbuf[0][node * 64 + half * 32];
#pragma unroll
        for (int c4 = 0; c4 < 8; c4++) {
            float4 v;
            v.x = fmaxf(acc[c4 * 4 + 0] + b1[half * 32 + c4 * 4 + 0], 0.f);
            v.y = fmaxf(acc[c4 * 4 + 1] + b1[half * 32 + c4 * 4 + 1], 0.f);
            v.z = fmaxf(acc[c4 * 4 + 2] + b1[half * 32 + c4 * 4 + 2], 0.f);
            v.w = fmaxf(acc[c4 * 4 + 3] + b1[half * 32 + c4 * 4 + 3], 0.f);
            *(float4*)&px[c4 * 4] = v;
            *(float4*)&ph[c4 * 4] = v;
        }
    }
}

// ---------------- preprocessing ----------------
__global__ void k_zero_detect(const int* ei32) {
    int i = blockIdx.x * blockDim.x + threadIdx.x;
    if (i < NN) g_cnt[i] = 0;
    if (i == 0) {
        int all0 = 1;
        for (int j = 0; j < 64; j++)
            if (ei32[2 * j + 1] != 0) all0 = 0;
        g_is64 = all0;
    }
}

__global__ void k_count(const void* eiv) {
    int e = blockIdx.x * blockDim.x + threadIdx.x;
    if (e >= EE) return;
    int d;
    if (g_is64) d = (int)((const long long*)eiv)[EE + e];
    else        d = ((const int*)eiv)[EE + e];
    atomicAdd(&g_cnt[d], 1);
}

__global__ __launch_bounds__(1024) void k_scanA() {
    __shared__ int wsum[32];
    int t = threadIdx.x, b = blockIdx.x;
    int i = b * 1024 + t;
    int v = (i < NN) ? g_cnt[i] : 0;
    int lane = t & 31, wid = t >> 5;
    int s = v;
#pragma unroll
    for (int o = 1; o < 32; o <<= 1) {
        int u = __shfl_up_sync(0xffffffffu, s, o);
        if (lane >= o) s += u;
    }
    if (lane == 31) wsum[wid] = s;
    __syncthreads();
    if (wid == 0) {
        int ws = wsum[lane];
#pragma unroll
        for (int o = 1; o < 32; o <<= 1) {
            int u = __shfl_up_sync(0xffffffffu, ws, o);
            if (lane >= o) ws += u;
        }
        wsum[lane] = ws;
    }
    __syncthreads();
    int excl = s - v + (wid > 0 ? wsum[wid - 1] : 0);
    if (i < NN) g_rowptr[i] = excl;
    if (t == 1023) g_bsum[b] = excl + v;
}

__global__ void k_scanB() {
    int t = threadIdx.x;  // 64 threads
    __shared__ int sh[64];
    sh[t] = (t < NBLK) ? g_bsum[t] : 0;
    __syncthreads();
    for (int o = 1; o < 64; o <<= 1) {
        int u = (t >= o) ? sh[t - o] : 0;
        __syncthreads();
        sh[t] += u;
        __syncthreads();
    }
    if (t < NBLK) g_boff[t] = sh[t] - g_bsum[t];
}

__global__ void k_scanC() {
    int i = blockIdx.x * blockDim.x + threadIdx.x;
    if (i < NN) {
        g_rowptr[i] += g_boff[i >> 10];
        g_dinv[i] = rsqrtf((float)(g_cnt[i] + 1));
        g_fill[i] = 0;
    }
    if (i == 0) g_rowptr[NN] = EE;
}

__global__ void k_fill(const void* eiv) {
    int e = blockIdx.x * blockDim.x + threadIdx.x;
    if (e >= EE) return;
    int s, d;
    if (g_is64) {
        const long long* ei = (const long long*)eiv;
        s = (int)ei[e];
        d = (int)ei[EE + e];
    } else {
        const int* ei = (const int*)eiv;
        s = ei[e];
        d = ei[EE + e];
    }
    int pos = g_rowptr[d] + atomicAdd(&g_fill[d], 1);
    g_col[pos] = s;
    g_val[pos] = g_dinv[s] * g_dinv[d];
}

// ---------------- fused GCNII layer ----------------
// warp = 4 nodes. Gather: lane owns 4 features ((lane&15)*4), half-warps
// split edge pairs -> LDG.128 per lane, 2 edges per step, 8-edge unroll.
__global__ __launch_bounds__(256) void k_layer(const float* __restrict__ W,
                                               float beta, int p) {
    __shared__ float ws[64 * 64];
    __shared__ float4 zq[8][64];
    int t = threadIdx.x, w = t >> 5, lane = t & 31;
    int l2 = lane * 2;
    int hl = lane >> 4;          // half id: edge parity within pair
    int fl = lane & 15;          // feature quad id
    for (int i = t; i < 4096; i += 256) ws[i] = W[i];
    __syncthreads();

    const float4* __restrict__ hin4 = (const float4*)g_hbuf[p];
    const float4* __restrict__ x04 = (const float4*)g_x0;
    float* __restrict__ hout = g_hbuf[p ^ 1];
    int warpG = blockIdx.x * 8 + w;
    int nW = gridDim.x * 8;
    float ob = 1.f - beta;

    for (int base = warpG * 4; base < NN; base += nW * 4) {
        float4 z4[4];
#pragma unroll
        for (int q = 0; q < 4; q++) {
            int node = base + q;
            if (node >= NN) { z4[q] = make_float4(0.f, 0.f, 0.f, 0.f); continue; }
            float4 acc = make_float4(0.f, 0.f, 0.f, 0.f);
            int e0 = g_rowptr[node], e1 = g_rowptr[node + 1];
            for (int eb = e0; eb < e1; eb += 32) {
                int ee = eb + lane;
                bool okl = ee < e1;
                int cc = okl ? g_col[ee] : 0;
                float vv = okl ? g_val[ee] : 0.f;
                int cn = min(32, e1 - eb);
                for (int j = 0; j < cn; j += 8) {
                    int sA = __shfl_sync(0xffffffffu, cc, j + hl);
                    int sB = __shfl_sync(0xffffffffu, cc, j + 2 + hl);
                    int sC = __shfl_sync(0xffffffffu, cc, j + 4 + hl);
                    int sD = __shfl_sync(0xffffffffu, cc, j + 6 + hl);
                    float vA = __shfl_sync(0xffffffffu, vv, j + hl);
                    float vB = __shfl_sync(0xffffffffu, vv, j + 2 + hl);
                    float vC = __shfl_sync(0xffffffffu, vv, j + 4 + hl);
                    float vD = __shfl_sync(0xffffffffu, vv, j + 6 + hl);
                    float4 hA = hin4[sA * 16 + fl];
                    float4 hB = hin4[sB * 16 + fl];
                    float4 hC = hin4[sC * 16 + fl];
                    float4 hD = hin4[sD * 16 + fl];
                    acc.x += vA * hA.x; acc.y += vA * hA.y;
                    acc.z += vA * hA.z; acc.w += vA * hA.w;
                    acc.x += vB * hB.x; acc.y += vB * hB.y;
                    acc.z += vB * hB.z; acc.w += vB * hB.w;
                    acc.x += vC * hC.x; acc.y += vC * hC.y;
                    acc.z += vC * hC.z; acc.w += vC * hC.w;
                    acc.x += vD * hD.x; acc.y += vD * hD.y;
                    acc.z += vD * hD.z; acc.w += vD * hD.w;
                }
            }
            // combine the two half-warp partial sums
            acc.x += __shfl_xor_sync(0xffffffffu, acc.x, 16);
            acc.y += __shfl_xor_sync(0xffffffffu, acc.y, 16);
            acc.z += __shfl_xor_sync(0xffffffffu, acc.z, 16);
            acc.w += __shfl_xor_sync(0xffffffffu, acc.w, 16);
            if (hl == 0) {
                float di = g_dinv[node];
                float dd = di * di;
                float4 hme = hin4[node * 16 + fl];
                float4 xm = x04[node * 16 + fl];
                z4[q].x = 0.5f * (acc.x + dd * hme.x) + 0.5f * xm.x;
                z4[q].y = 0.5f * (acc.y + dd * hme.y) + 0.5f * xm.y;
                z4[q].z = 0.5f * (acc.z + dd * hme.z) + 0.5f * xm.z;
                z4[q].w = 0.5f * (acc.w + dd * hme.w) + 0.5f * xm.w;
            }
        }
        // stage transposed: zq[k] = {zA[k], zB[k], zC[k], zD[k]}
        if (hl == 0) {
            zq[w][fl * 4 + 0] = make_float4(z4[0].x, z4[1].x, z4[2].x, z4[3].x);
            zq[w][fl * 4 + 1] = make_float4(z4[0].y, z4[1].y, z4[2].y, z4[3].y);
            zq[w][fl * 4 + 2] = make_float4(z4[0].z, z4[1].z, z4[2].z, z4[3].z);
            zq[w][fl * 4 + 3] = make_float4(z4[0].w, z4[1].w, z4[2].w, z4[3].w);
        }
        __syncwarp();

        float4 s0 = make_float4(0.f, 0.f, 0.f, 0.f);  // out col l2, nodes A..D
        float4 s1 = make_float4(0.f, 0.f, 0.f, 0.f);  // out col l2+1
#pragma unroll
        for (int k = 0; k < 64; k++) {
            float4 zk = zq[w][k];
            float2 wk = *(const float2*)&ws[k * 64 + l2];
            s0.x += zk.x * wk.x; s0.y += zk.y * wk.x;
            s0.z += zk.z * wk.x; s0.w += zk.w * wk.x;
            s1.x += zk.x * wk.y; s1.y += zk.y * wk.y;
            s1.z += zk.z * wk.y; s1.w += zk.w * wk.y;
        }
        float4 zc0 = zq[w][l2];      // z at col l2 for nodes A..D
        float4 zc1 = zq[w][l2 + 1];
        float zr0[4] = {zc0.x, zc0.y, zc0.z, zc0.w};
        float zr1[4] = {zc1.x, zc1.y, zc1.z, zc1.w};
        float sc0[4] = {s0.x, s0.y, s0.z, s0.w};
        float sc1[4] = {s1.x, s1.y, s1.z, s1.w};
#pragma unroll
        for (int q = 0; q < 4; q++) {
            int node = base + q;
            if (node < NN) {
                float o0 = fmaxf(ob * zr0[q] + beta * sc0[q], 0.f);
                float o1 = fmaxf(ob * zr1[q] + beta * sc1[q], 0.f);
                *(float2*)&hout[node * 64 + l2] = make_float2(o0, o1);
            }
        }
        __syncwarp();
    }
}

// ---------------- output: lin2 + log_softmax ----------------
__global__ __launch_bounds__(256) void k_out(const float* __restrict__ w2,
                                             const float* __restrict__ b2,
                                             float* __restrict__ out) {
    __shared__ float ws[64 * OC];
    __shared__ float bs[OC];
    __shared__ float zsm[8][64];
    int t = threadIdx.x, w = t >> 5, lane = t & 31;
    for (int i = t; i < 64 * OC; i += 256) ws[i] = w2[i];
    if (t < OC) bs[t] = b2[t];
    __syncthreads();

    const float* h = g_hbuf[0];  // NL even -> final state in buffer 0
    int warpG = blockIdx.x * 8 + w;
    int nW = gridDim.x * 8;

    for (int node = warpG; node < NN; node += nW) {
        float2 h2 = *(const float2*)&h[node * 64 + lane * 2];
        *(float2*)&zsm[w][lane * 2] = h2;
        __syncwarp();
        int c0 = lane;
        int c1 = lane + 32;
        float v0 = bs[c0];
        float v1 = (lane < 8) ? bs[c1] : 0.f;
#pragma unroll
        for (int k = 0; k < 64; k++) {
            float zk = zsm[w][k];
            v0 += zk * ws[k * OC + c0];
            if (lane < 8) v1 += zk * ws[k * OC + c1];
        }
        float m = v0;
        if (lane < 8) m = fmaxf(m, v1);
#pragma unroll
        for (int o = 16; o > 0; o >>= 1)
            m = fmaxf(m, __shfl_xor_sync(0xffffffffu, m, o));
        float se = expf(v0 - m) + ((lane < 8) ? expf(v1 - m) : 0.f);
#pragma unroll
        for (int o = 16; o > 0; o >>= 1)
            se += __shfl_xor_sync(0xffffffffu, se, o);
        float lse = m + logf(se);
        out[node * OC + c0] = v0 - lse;
        if (lane < 8) out[node * OC + c1] = v1 - lse;
        __syncwarp();
    }
}

// ---------------- launch ----------------
extern "C" void kernel_launch(void* const* d_in, const int* in_sizes, int n_in,
                              void* d_out, int out_size) {
    (void)in_sizes; (void)n_in; (void)out_size;
    const float* x  = (const float*)d_in[0];
    const void*  ei = d_in[1];
    const float* w1 = (const float*)d_in[2];
    const float* b1 = (const float*)d_in[3];
    const float* cw = (const float*)d_in[4];
    const float* w2 = (const float*)d_in[5];
    const float* b2 = (const float*)d_in[6];
    float* out = (float*)d_out;

    k_lin1<<<(NN + 127) / 128, 256>>>(x, w1, b1);
    k_zero_detect<<<(NN + 1023) / 1024, 1024>>>((const int*)ei);
    k_count<<<(EE + 255) / 256, 256>>>(ei);
    k_scanA<<<NBLK, 1024>>>();
    k_scanB<<<1, 64>>>();
    k_scanC<<<(NN + 1023) / 1024, 1024>>>();
    k_fill<<<(EE + 255) / 256, 256>>>(ei);

    for (int l = 0; l < NL; l++) {
        float beta = logf(1.0f / (float)(l + 1) + 1.0f);
        k_layer<<<148 * 8, 256>>>(cw + (size_t)l * HH * HH, beta, l & 1);
    }
    k_out<<<512, 256>>>(w2, b2, out);
}